// round 1
// baseline (speedup 1.0000x reference)
#include <cuda_runtime.h>
#include <math.h>

// Problem dims
#define EMB   768
#define NHEAD 12
#define HDIM  64
#define SEQ   1024
#define BATCH 8
#define MTOT  (BATCH * SEQ)     // 8192
#define FQKV  (3 * EMB)         // 2304
#define BHTOT (BATCH * NHEAD)   // 96

// Scratch (allocation-free rule: __device__ globals)
__device__ float g_qkv[(size_t)MTOT * FQKV];   // 75.5 MB : qkv = x@Wqkv^T + b
__device__ float g_oh [(size_t)MTOT * EMB];    // 25.2 MB : attn@V gathered per head

// ---------------------------------------------------------------------------
// Generic 64x64 tile GEMM, 256 threads (16x16), each thread 4x4.
// BT = true : C = A * B^T   (A: MxK row-major, B: NxK row-major)
// BT = false: C = A * B     (A: MxK row-major, B: KxN row-major)
// All dims used are multiples of the tile sizes -> no bounds checks.
// ---------------------------------------------------------------------------
template<bool BT>
__device__ __forceinline__ void gemm64(
    const float* __restrict__ A, int lda,
    const float* __restrict__ B, int ldb,
    float*       __restrict__ C, int ldc,
    int row0, int col0, int K,
    const float* __restrict__ bias, float scale)
{
    __shared__ float As[16][68];
    __shared__ float Bs[16][68];
    const int tx = threadIdx.x;     // 0..15
    const int ty = threadIdx.y;     // 0..15
    const int t  = ty * 16 + tx;    // 0..255

    float acc[4][4] = {};

    for (int k0 = 0; k0 < K; k0 += 16) {
        // Load A tile: 64 rows x 16 k  (k contiguous in gmem)
        #pragma unroll
        for (int i = 0; i < 4; i++) {
            int idx = t + i * 256;
            int r  = idx >> 4;
            int kk = idx & 15;
            As[kk][r] = A[(size_t)(row0 + r) * lda + k0 + kk];
        }
        // Load B tile
        if (BT) {
            #pragma unroll
            for (int i = 0; i < 4; i++) {
                int idx = t + i * 256;
                int r  = idx >> 4;
                int kk = idx & 15;
                Bs[kk][r] = B[(size_t)(col0 + r) * ldb + k0 + kk];
            }
        } else {
            #pragma unroll
            for (int i = 0; i < 4; i++) {
                int idx = t + i * 256;
                int kk = idx >> 6;       // 0..15
                int c  = idx & 63;       // 0..63
                Bs[kk][c] = B[(size_t)(k0 + kk) * ldb + col0 + c];
            }
        }
        __syncthreads();

        #pragma unroll
        for (int kk = 0; kk < 16; kk++) {
            float a[4], b[4];
            #pragma unroll
            for (int i = 0; i < 4; i++) a[i] = As[kk][ty * 4 + i];
            #pragma unroll
            for (int j = 0; j < 4; j++) b[j] = Bs[kk][tx * 4 + j];
            #pragma unroll
            for (int i = 0; i < 4; i++)
                #pragma unroll
                for (int j = 0; j < 4; j++)
                    acc[i][j] += a[i] * b[j];
        }
        __syncthreads();
    }

    #pragma unroll
    for (int i = 0; i < 4; i++) {
        int r = row0 + ty * 4 + i;
        #pragma unroll
        for (int j = 0; j < 4; j++) {
            int c = col0 + tx * 4 + j;
            float v = acc[i][j] * scale;
            if (bias) v += bias[c];
            C[(size_t)r * ldc + c] = v;
        }
    }
}

// ---------------------------------------------------------------------------
// 1) qkv = x @ Wqkv^T + b_qkv      (8192x768) @ (2304x768)^T -> 8192x2304
// ---------------------------------------------------------------------------
__global__ void __launch_bounds__(256) k_qkv(const float* __restrict__ x,
                                             const float* __restrict__ w,
                                             const float* __restrict__ b)
{
    gemm64<true>(x, EMB, w, EMB, g_qkv, FQKV,
                 blockIdx.y * 64, blockIdx.x * 64, EMB, b, 1.0f);
}

// ---------------------------------------------------------------------------
// 2) scores[b,h] = Q K^T * scale   (1024x64)@(1024x64)^T per (b,h)
// ---------------------------------------------------------------------------
__global__ void __launch_bounds__(256) k_scores(float* __restrict__ attn)
{
    int bh = blockIdx.z;
    int bb = bh / NHEAD, h = bh % NHEAD;
    const float* Q = g_qkv + (size_t)bb * SEQ * FQKV + h * HDIM;
    const float* K = g_qkv + (size_t)bb * SEQ * FQKV + EMB + h * HDIM;
    float* C = attn + (size_t)bh * SEQ * SEQ;
    gemm64<true>(Q, FQKV, K, FQKV, C, SEQ,
                 blockIdx.y * 64, blockIdx.x * 64, HDIM, nullptr, 0.125f);
}

// ---------------------------------------------------------------------------
// 3) row-wise softmax over 1024, in place. One block per row, 256 threads.
// ---------------------------------------------------------------------------
__global__ void __launch_bounds__(256) k_softmax(float* __restrict__ attn)
{
    size_t row = blockIdx.x;
    float* p = attn + row * SEQ;
    int t = threadIdx.x;

    float4 v = reinterpret_cast<float4*>(p)[t];

    __shared__ float redm[8];
    __shared__ float reds[8];

    float m = fmaxf(fmaxf(v.x, v.y), fmaxf(v.z, v.w));
    #pragma unroll
    for (int o = 16; o > 0; o >>= 1) m = fmaxf(m, __shfl_xor_sync(0xffffffffu, m, o));
    if ((t & 31) == 0) redm[t >> 5] = m;
    __syncthreads();
    float mAll = redm[0];
    #pragma unroll
    for (int i = 1; i < 8; i++) mAll = fmaxf(mAll, redm[i]);

    v.x = __expf(v.x - mAll);
    v.y = __expf(v.y - mAll);
    v.z = __expf(v.z - mAll);
    v.w = __expf(v.w - mAll);

    float s = v.x + v.y + v.z + v.w;
    #pragma unroll
    for (int o = 16; o > 0; o >>= 1) s += __shfl_xor_sync(0xffffffffu, s, o);
    if ((t & 31) == 0) reds[t >> 5] = s;
    __syncthreads();
    float sAll = 0.0f;
    #pragma unroll
    for (int i = 0; i < 8; i++) sAll += reds[i];

    float inv = 1.0f / sAll;
    v.x *= inv; v.y *= inv; v.z *= inv; v.w *= inv;
    reinterpret_cast<float4*>(p)[t] = v;
}

// ---------------------------------------------------------------------------
// 4) oh[b,:,h,:] = attn[b,h] @ V[b,h]   (1024x1024)@(1024x64)
// ---------------------------------------------------------------------------
__global__ void __launch_bounds__(256) k_av(const float* __restrict__ attn)
{
    int bh = blockIdx.z;
    int bb = bh / NHEAD, h = bh % NHEAD;
    const float* A = attn + (size_t)bh * SEQ * SEQ;                     // 1024x1024
    const float* V = g_qkv + (size_t)bb * SEQ * FQKV + 2 * EMB + h * HDIM; // K x 64, ldb FQKV
    float* C = g_oh + (size_t)bb * SEQ * EMB + h * HDIM;                // ldc EMB
    gemm64<false>(A, SEQ, V, FQKV, C, EMB,
                  blockIdx.y * 64, 0, SEQ, nullptr, 1.0f);
}

// ---------------------------------------------------------------------------
// 5) out = oh @ Wout^T + b_out     (8192x768)@(768x768)^T
// ---------------------------------------------------------------------------
__global__ void __launch_bounds__(256) k_out(const float* __restrict__ w,
                                             const float* __restrict__ b,
                                             float* __restrict__ out)
{
    gemm64<true>(g_oh, EMB, w, EMB, out, EMB,
                 blockIdx.y * 64, blockIdx.x * 64, EMB, b, 1.0f);
}

// ---------------------------------------------------------------------------
extern "C" void kernel_launch(void* const* d_in, const int* in_sizes, int n_in,
                              void* d_out, int out_size)
{
    const float* x     = (const float*)d_in[0];
    const float* w_qkv = (const float*)d_in[1];
    const float* b_qkv = (const float*)d_in[2];
    const float* w_out = (const float*)d_in[3];
    const float* b_out = (const float*)d_in[4];

    float* out  = (float*)d_out;                       // 8192*768
    float* attn = out + (size_t)MTOT * EMB;            // 96*1024*1024

    dim3 thr(16, 16);

    // 1) QKV projection
    k_qkv<<<dim3(FQKV / 64, MTOT / 64), thr>>>(x, w_qkv, b_qkv);

    // 2) scores = QK^T * scale
    k_scores<<<dim3(SEQ / 64, SEQ / 64, BHTOT), thr>>>(attn);

    // 3) softmax in place
    k_softmax<<<BHTOT * SEQ, 256>>>(attn);

    // 4) attn @ V
    k_av<<<dim3(1, SEQ / 64, BHTOT), thr>>>(attn);

    // 5) output projection
    k_out<<<dim3(EMB / 64, MTOT / 64), thr>>>(w_out, b_out, out);
}

// round 2
// speedup vs baseline: 1.6005x; 1.6005x over previous
#include <cuda_runtime.h>
#include <math.h>
#include <stdint.h>

// Problem dims
#define EMB   768
#define NHEAD 12
#define HDIM  64
#define SEQ   1024
#define BATCH 8
#define MTOT  (BATCH * SEQ)     // 8192
#define FQKV  (3 * EMB)         // 2304
#define BHTOT (BATCH * NHEAD)   // 96

// Scratch (allocation-free rule: __device__ globals)
__device__ float g_qkv[(size_t)MTOT * FQKV];   // 75.5 MB
__device__ float g_oh [(size_t)MTOT * EMB];    // 25.2 MB

// ---------------------------------------------------------------------------
// tf32 helpers
// ---------------------------------------------------------------------------
__device__ __forceinline__ uint32_t f2tf(float x) {
    uint32_t r;
    asm("cvt.rna.tf32.f32 %0, %1;" : "=r"(r) : "f"(x));
    return r;
}

__device__ __forceinline__ void mma8(float* c,
                                     uint32_t a0, uint32_t a1, uint32_t a2, uint32_t a3,
                                     uint32_t b0, uint32_t b1)
{
    asm volatile(
        "mma.sync.aligned.m16n8k8.row.col.f32.tf32.tf32.f32 "
        "{%0,%1,%2,%3}, {%4,%5,%6,%7}, {%8,%9}, {%0,%1,%2,%3};\n"
        : "+f"(c[0]), "+f"(c[1]), "+f"(c[2]), "+f"(c[3])
        : "r"(a0), "r"(a1), "r"(a2), "r"(a3), "r"(b0), "r"(b1));
}

// ---------------------------------------------------------------------------
// tf32 tensor-core GEMM. Block tile 128x64, 256 threads (8 warps, 2x4).
// Warp tile 64x16 = 4 m16 tiles x 2 n8 tiles.  K chunk = 32 (4 k8 steps).
// BT    = true : C = A * B^T  (A MxK row-major, B NxK row-major)
//         false: C = A * B    (B KxN row-major)
// SPLIT = true : 3xTF32 hi/lo decomposition (near-fp32 accuracy)
// All dims multiples of tiles -> no bounds checks.
// ---------------------------------------------------------------------------
template<bool BT, bool SPLIT>
__device__ __forceinline__ void mma_gemm(
    const float* __restrict__ A, int lda,
    const float* __restrict__ B, int ldb,
    float*       __restrict__ C, int ldc,
    int row0, int col0, int K,
    const float* __restrict__ bias, float scale)
{
    __shared__ float As[128][36];   // row stride 36: conflict-free frag loads
    __shared__ float Bs[64][36];

    const int t    = threadIdx.x;
    const int warp = t >> 5, lane = t & 31;
    const int wm   = warp >> 2, wn = warp & 3;
    const int g    = lane >> 2, tg = lane & 3;

    float acc[4][2][4] = {};

    for (int k0 = 0; k0 < K; k0 += 32) {
        // ---- load A tile: 128 rows x 32 k (float4 along k) ----
        #pragma unroll
        for (int i = 0; i < 4; i++) {
            int idx = t + i * 256;
            int r = idx >> 3, c4 = (idx & 7) * 4;
            float4 v = *reinterpret_cast<const float4*>(
                &A[(size_t)(row0 + r) * lda + k0 + c4]);
            As[r][c4 + 0] = v.x; As[r][c4 + 1] = v.y;
            As[r][c4 + 2] = v.z; As[r][c4 + 3] = v.w;
        }
        // ---- load B tile into Bs[n][k] ----
        if (BT) {
            #pragma unroll
            for (int i = 0; i < 2; i++) {
                int idx = t + i * 256;
                int r = idx >> 3, c4 = (idx & 7) * 4;
                float4 v = *reinterpret_cast<const float4*>(
                    &B[(size_t)(col0 + r) * ldb + k0 + c4]);
                Bs[r][c4 + 0] = v.x; Bs[r][c4 + 1] = v.y;
                Bs[r][c4 + 2] = v.z; Bs[r][c4 + 3] = v.w;
            }
        } else {
            #pragma unroll
            for (int i = 0; i < 2; i++) {
                int idx = t + i * 256;
                int k = idx >> 4, n4 = (idx & 15) * 4;
                float4 v = *reinterpret_cast<const float4*>(
                    &B[(size_t)(k0 + k) * ldb + col0 + n4]);
                Bs[n4 + 0][k] = v.x; Bs[n4 + 1][k] = v.y;
                Bs[n4 + 2][k] = v.z; Bs[n4 + 3][k] = v.w;
            }
        }
        __syncthreads();

        // ---- 4 k8 steps ----
        #pragma unroll
        for (int ks = 0; ks < 4; ks++) {
            const int kb = ks * 8;
            uint32_t ah[4][4], al[4][4], bh[2][2], bl[2][2];

            #pragma unroll
            for (int mi = 0; mi < 4; mi++) {
                int r = wm * 64 + mi * 16;
                float v0 = As[r + g    ][kb + tg];
                float v1 = As[r + g + 8][kb + tg];
                float v2 = As[r + g    ][kb + tg + 4];
                float v3 = As[r + g + 8][kb + tg + 4];
                ah[mi][0] = f2tf(v0); ah[mi][1] = f2tf(v1);
                ah[mi][2] = f2tf(v2); ah[mi][3] = f2tf(v3);
                if (SPLIT) {
                    al[mi][0] = f2tf(v0 - __uint_as_float(ah[mi][0]));
                    al[mi][1] = f2tf(v1 - __uint_as_float(ah[mi][1]));
                    al[mi][2] = f2tf(v2 - __uint_as_float(ah[mi][2]));
                    al[mi][3] = f2tf(v3 - __uint_as_float(ah[mi][3]));
                }
            }
            #pragma unroll
            for (int ni = 0; ni < 2; ni++) {
                int c = wn * 16 + ni * 8;
                float w0 = Bs[c + g][kb + tg];
                float w1 = Bs[c + g][kb + tg + 4];
                bh[ni][0] = f2tf(w0); bh[ni][1] = f2tf(w1);
                if (SPLIT) {
                    bl[ni][0] = f2tf(w0 - __uint_as_float(bh[ni][0]));
                    bl[ni][1] = f2tf(w1 - __uint_as_float(bh[ni][1]));
                }
            }

            #pragma unroll
            for (int mi = 0; mi < 4; mi++)
                #pragma unroll
                for (int ni = 0; ni < 2; ni++) {
                    float* c = acc[mi][ni];
                    mma8(c, ah[mi][0], ah[mi][1], ah[mi][2], ah[mi][3],
                            bh[ni][0], bh[ni][1]);
                    if (SPLIT) {
                        mma8(c, ah[mi][0], ah[mi][1], ah[mi][2], ah[mi][3],
                                bl[ni][0], bl[ni][1]);
                        mma8(c, al[mi][0], al[mi][1], al[mi][2], al[mi][3],
                                bh[ni][0], bh[ni][1]);
                    }
                }
        }
        __syncthreads();
    }

    // ---- epilogue: float2 stores ----
    #pragma unroll
    for (int mi = 0; mi < 4; mi++) {
        int r0 = row0 + wm * 64 + mi * 16 + g;
        #pragma unroll
        for (int ni = 0; ni < 2; ni++) {
            int c = col0 + wn * 16 + ni * 8 + 2 * tg;
            float b0 = bias ? bias[c]     : 0.0f;
            float b1 = bias ? bias[c + 1] : 0.0f;
            float2 v0 = make_float2(acc[mi][ni][0] * scale + b0,
                                    acc[mi][ni][1] * scale + b1);
            float2 v1 = make_float2(acc[mi][ni][2] * scale + b0,
                                    acc[mi][ni][3] * scale + b1);
            *reinterpret_cast<float2*>(&C[(size_t)r0       * ldc + c]) = v0;
            *reinterpret_cast<float2*>(&C[(size_t)(r0 + 8) * ldc + c]) = v1;
        }
    }
}

// ---------------------------------------------------------------------------
// 1) qkv = x @ Wqkv^T + b  (SPLIT: feeds everything downstream)
__global__ void __launch_bounds__(256) k_qkv(const float* __restrict__ x,
                                             const float* __restrict__ w,
                                             const float* __restrict__ b)
{
    mma_gemm<true, true>(x, EMB, w, EMB, g_qkv, FQKV,
                         blockIdx.y * 128, blockIdx.x * 64, EMB, b, 1.0f);
}

// 2) scores = Q K^T * scale  (SPLIT: softmax is error-sensitive)
__global__ void __launch_bounds__(256) k_scores(float* __restrict__ attn)
{
    int bh = blockIdx.z;
    int bb = bh / NHEAD, h = bh % NHEAD;
    const float* Q = g_qkv + (size_t)bb * SEQ * FQKV + h * HDIM;
    const float* K = g_qkv + (size_t)bb * SEQ * FQKV + EMB + h * HDIM;
    float* C = attn + (size_t)bh * SEQ * SEQ;
    mma_gemm<true, true>(Q, FQKV, K, FQKV, C, SEQ,
                         blockIdx.y * 128, blockIdx.x * 64, HDIM, nullptr, 0.125f);
}

// 3) row softmax over 1024, in place
__global__ void __launch_bounds__(256) k_softmax(float* __restrict__ attn)
{
    size_t row = blockIdx.x;
    float* p = attn + row * SEQ;
    int t = threadIdx.x;

    float4 v = reinterpret_cast<float4*>(p)[t];

    __shared__ float redm[8];
    __shared__ float reds[8];

    float m = fmaxf(fmaxf(v.x, v.y), fmaxf(v.z, v.w));
    #pragma unroll
    for (int o = 16; o > 0; o >>= 1) m = fmaxf(m, __shfl_xor_sync(0xffffffffu, m, o));
    if ((t & 31) == 0) redm[t >> 5] = m;
    __syncthreads();
    float mAll = redm[0];
    #pragma unroll
    for (int i = 1; i < 8; i++) mAll = fmaxf(mAll, redm[i]);

    v.x = __expf(v.x - mAll);
    v.y = __expf(v.y - mAll);
    v.z = __expf(v.z - mAll);
    v.w = __expf(v.w - mAll);

    float s = v.x + v.y + v.z + v.w;
    #pragma unroll
    for (int o = 16; o > 0; o >>= 1) s += __shfl_xor_sync(0xffffffffu, s, o);
    if ((t & 31) == 0) reds[t >> 5] = s;
    __syncthreads();
    float sAll = 0.0f;
    #pragma unroll
    for (int i = 0; i < 8; i++) sAll += reds[i];

    float inv = 1.0f / sAll;
    v.x *= inv; v.y *= inv; v.z *= inv; v.w *= inv;
    reinterpret_cast<float4*>(p)[t] = v;
}

// 4) oh = attn @ V  (plain tf32: averaging washes out rounding)
__global__ void __launch_bounds__(256) k_av(const float* __restrict__ attn)
{
    int bh = blockIdx.z;
    int bb = bh / NHEAD, h = bh % NHEAD;
    const float* A = attn + (size_t)bh * SEQ * SEQ;
    const float* V = g_qkv + (size_t)bb * SEQ * FQKV + 2 * EMB + h * HDIM;
    float* C = g_oh + (size_t)bb * SEQ * EMB + h * HDIM;
    mma_gemm<false, false>(A, SEQ, V, FQKV, C, EMB,
                           blockIdx.y * 128, 0, SEQ, nullptr, 1.0f);
}

// 5) out = oh @ Wout^T + b
__global__ void __launch_bounds__(256) k_out(const float* __restrict__ w,
                                             const float* __restrict__ b,
                                             float* __restrict__ out)
{
    mma_gemm<true, false>(g_oh, EMB, w, EMB, out, EMB,
                          blockIdx.y * 128, blockIdx.x * 64, EMB, b, 1.0f);
}

// ---------------------------------------------------------------------------
extern "C" void kernel_launch(void* const* d_in, const int* in_sizes, int n_in,
                              void* d_out, int out_size)
{
    const float* x     = (const float*)d_in[0];
    const float* w_qkv = (const float*)d_in[1];
    const float* b_qkv = (const float*)d_in[2];
    const float* w_out = (const float*)d_in[3];
    const float* b_out = (const float*)d_in[4];

    float* out  = (float*)d_out;                       // 8192*768
    float* attn = out + (size_t)MTOT * EMB;            // 96*1024*1024

    // 1) QKV projection
    k_qkv<<<dim3(FQKV / 64, MTOT / 128), 256>>>(x, w_qkv, b_qkv);

    // 2) scores = QK^T * scale
    k_scores<<<dim3(SEQ / 64, SEQ / 128, BHTOT), 256>>>(attn);

    // 3) softmax in place
    k_softmax<<<BHTOT * SEQ, 256>>>(attn);

    // 4) attn @ V
    k_av<<<dim3(1, SEQ / 128, BHTOT), 256>>>(attn);

    // 5) output projection
    k_out<<<dim3(EMB / 64, MTOT / 128), 256>>>(w_out, b_out, out);
}